// round 10
// baseline (speedup 1.0000x reference)
#include <cuda_runtime.h>
#include <cuda_bf16.h>
#include <math.h>

#define BS 8
#define D 256
#define L 1024
#define H 8
#define DK 32
#define EPSV 1e-8f

typedef unsigned int u32;
typedef unsigned long long u64;

// ---- f32x2 packed-math helpers (proj kernel) --------------------------------
__device__ __forceinline__ u64 f2dup(float x) {
    u64 r; asm("mov.b64 %0, {%1, %1};" : "=l"(r) : "f"(x)); return r;
}
__device__ __forceinline__ u64 f2pack(float lo, float hi) {
    u64 r; asm("mov.b64 %0, {%1, %2};" : "=l"(r) : "f"(lo), "f"(hi)); return r;
}
__device__ __forceinline__ void fma2(u64& d, u64 a, u64 b) {
    asm("fma.rn.f32x2 %0, %1, %2, %0;" : "+l"(d) : "l"(a), "l"(b));
}
__device__ __forceinline__ float2 f2unpack(u64 v) {
    float2 f; asm("mov.b64 {%0, %1}, %2;" : "=f"(f.x), "=f"(f.y) : "l"(v)); return f;
}

// ---- tensor-core helpers ----------------------------------------------------
__device__ __forceinline__ u32 smaddr(const void* p) {
    return (u32)__cvta_generic_to_shared(p);
}
__device__ __forceinline__ void ldsm4(u32& r0, u32& r1, u32& r2, u32& r3, u32 a) {
    asm volatile("ldmatrix.sync.aligned.m8n8.x4.shared.b16 {%0,%1,%2,%3}, [%4];"
        : "=r"(r0), "=r"(r1), "=r"(r2), "=r"(r3) : "r"(a));
}
__device__ __forceinline__ void ldsm4t(u32& r0, u32& r1, u32& r2, u32& r3, u32 a) {
    asm volatile("ldmatrix.sync.aligned.m8n8.x4.trans.shared.b16 {%0,%1,%2,%3}, [%4];"
        : "=r"(r0), "=r"(r1), "=r"(r2), "=r"(r3) : "r"(a));
}
__device__ __forceinline__ void mma16816(float* c, const u32* a, u32 b0, u32 b1) {
    asm volatile("mma.sync.aligned.m16n8k16.row.col.f32.bf16.bf16.f32 "
        "{%0,%1,%2,%3}, {%4,%5,%6,%7}, {%8,%9}, {%0,%1,%2,%3};"
        : "+f"(c[0]), "+f"(c[1]), "+f"(c[2]), "+f"(c[3])
        : "r"(a[0]), "r"(a[1]), "r"(a[2]), "r"(a[3]), "r"(b0), "r"(b1));
}
__device__ __forceinline__ u32 cvtbf2(float hi, float lo) {
    u32 d; asm("cvt.rn.bf16x2.f32 %0, %1, %2;" : "=r"(d) : "f"(hi), "f"(lo)); return d;
}
// split x into (hi bf16 in low16, lo bf16 in high16)
__device__ __forceinline__ u32 packsplit(float x) {
    __nv_bfloat16 hb = __float2bfloat16(x);
    u32 hbits = (u32)__bfloat16_as_ushort(hb);
    float hf = __uint_as_float(hbits << 16);
    __nv_bfloat16 lb = __float2bfloat16(x - hf);
    return ((u32)__bfloat16_as_ushort(lb) << 16) | hbits;
}

// Scratch (device globals)
__device__ u32 g_qp[BS * D * L];    // [bh][c][l] packed (bf16 hi | lo<<16), pre-masked
__device__ u32 g_kp[BS * D * L];
__device__ u32 g_vp[BS * D * L];
__device__ u32 g_valp[BS * L * D];  // [b][l][c] packed attention output
__device__ u32 g_wps[D * D];        // [j][i] packed Wp (transposed)

// ---------------------------------------------------------------------------
// Kernel 0: split+transpose Wp into packed bf16 hi/lo plane [j][i].
// ---------------------------------------------------------------------------
__global__ __launch_bounds__(256) void wsplit_kernel(const float* __restrict__ Wp)
{
    int idx = blockIdx.x * 256 + threadIdx.x;
    int i = idx >> 8, j = idx & 255;
    g_wps[j * D + i] = packsplit(Wp[i * D + j]);
}

// ---------------------------------------------------------------------------
// Kernel 1: grouped 1x1 conv projection -> packed bf16 hi/lo planes.
// ---------------------------------------------------------------------------
__global__ __launch_bounds__(256) void proj_kernel(
    const float* __restrict__ q, const float* __restrict__ k,
    const float* __restrict__ v, const float* __restrict__ mask,
    const float* __restrict__ Wq, const float* __restrict__ Wk,
    const float* __restrict__ Wv)
{
    __shared__ float wt[DK * DK];   // wt[j][i] = W[i][j]
    const int h = blockIdx.y;
    const int z = blockIdx.z;
    const int b = z / 3;
    const int which = z - b * 3;
    const int t = threadIdx.x;

    const float* __restrict__ X = (which == 0) ? q : (which == 1) ? k : v;
    const float* __restrict__ W = (which == 0) ? Wq : (which == 1) ? Wk : Wv;
    u32* __restrict__ O = (which == 0) ? g_qp : (which == 1) ? g_kp : g_vp;

    for (int idx = t; idx < DK * DK; idx += 256) {
        int j = idx >> 5, i = idx & 31;
        wt[j * DK + i] = W[h * DK * DK + i * DK + j];
    }
    __syncthreads();

    const int l0 = blockIdx.x * 512 + t * 2;
    const float mv0 = mask[b * L + l0];
    const float mv1 = mask[b * L + l0 + 1];
    const int xbase = (b * D + h * DK) * L + l0;
    const int obase = (b * H + h) * DK * L + l0;

    u64 acc[2][16];
    #pragma unroll
    for (int p = 0; p < 2; p++)
        #pragma unroll
        for (int i = 0; i < 16; i++) acc[p][i] = 0ull;

    #pragma unroll
    for (int j = 0; j < DK; j++) {
        float2 xv = *(const float2*)&X[xbase + j * L];
        u64 x0 = f2dup(xv.x);
        u64 x1 = f2dup(xv.y);
        #pragma unroll
        for (int q4 = 0; q4 < 8; q4++) {
            float4 w4 = *(const float4*)&wt[j * DK + q4 * 4];
            u64 wp0 = f2pack(w4.x, w4.y);
            u64 wp1 = f2pack(w4.z, w4.w);
            fma2(acc[0][q4 * 2 + 0], x0, wp0);
            fma2(acc[0][q4 * 2 + 1], x0, wp1);
            fma2(acc[1][q4 * 2 + 0], x1, wp0);
            fma2(acc[1][q4 * 2 + 1], x1, wp1);
        }
    }

    #pragma unroll
    for (int ip = 0; ip < 16; ip++) {
        float2 r0 = f2unpack(acc[0][ip]);
        float2 r1 = f2unpack(acc[1][ip]);
        uint2 s0, s1;
        s0.x = packsplit(r0.x * mv0); s0.y = packsplit(r1.x * mv1);
        s1.x = packsplit(r0.y * mv0); s1.y = packsplit(r1.y * mv1);
        *(uint2*)&O[obase + (2 * ip + 0) * L] = s0;
        *(uint2*)&O[obase + (2 * ip + 1) * L] = s1;
    }
}

// ---------------------------------------------------------------------------
// Kernel 2: fused attention, bf16x3 tensor-core (mma.sync m16n8k16).
// CTA: 128 rows x full L loop, 8 warps, warp tile = 16 rows x 64 cols.
// ---------------------------------------------------------------------------
#define QP 48
#define KP 72
#define SM_QSH 0
#define SM_QSL 12288
#define SM_KSH 24576
#define SM_KSL 29184
#define SM_VSH 33792
#define SM_VSL 38400
#define SM_MK  43008
#define SM_TOT 43264

__global__ __launch_bounds__(256) void attn_kernel(const float* __restrict__ mask)
{
    extern __shared__ char smb[];
    unsigned short* Qsh = (unsigned short*)(smb + SM_QSH);  // [m][c]
    unsigned short* Qsl = (unsigned short*)(smb + SM_QSL);
    unsigned short* Ksh = (unsigned short*)(smb + SM_KSH);  // [c][n]
    unsigned short* Ksl = (unsigned short*)(smb + SM_KSL);
    unsigned short* Vsh = (unsigned short*)(smb + SM_VSH);  // [d][n]
    unsigned short* Vsl = (unsigned short*)(smb + SM_VSL);
    float* mk = (float*)(smb + SM_MK);

    const int bh = blockIdx.y;
    const int b = bh / H;
    const int row0 = blockIdx.x * 128;

    const u32* __restrict__ qb = g_qp + bh * DK * L;
    const u32* __restrict__ kbp = g_kp + bh * DK * L;
    const u32* __restrict__ vbp = g_vp + bh * DK * L;
    const float* __restrict__ mp = mask + b * L;

    const int t = threadIdx.x;
    const int lane = t & 31;
    const int warp = t >> 5;
    const int R0 = warp * 16;
    const int qid = lane & 3;

    // ---- Q fill: [m][c] hi/lo planes ----
    #pragma unroll
    for (int i = 0; i < 8; i++) {
        int idx = i * 256 + t;
        int m = idx >> 4, cp = idx & 15;
        u32 q0 = qb[(2 * cp + 0) * L + row0 + m];
        u32 q1 = qb[(2 * cp + 1) * L + row0 + m];
        *(u32*)&Qsh[m * QP + 2 * cp] = ((q1 & 0xFFFFu) << 16) | (q0 & 0xFFFFu);
        *(u32*)&Qsl[m * QP + 2 * cp] = (q1 & 0xFFFF0000u) | (q0 >> 16);
    }

    // ---- prefetch K/V tile 0 ----
    uint2 kpre[4], vpre[4];
    #pragma unroll
    for (int i = 0; i < 4; i++) {
        int idx = i * 256 + t;
        int c = idx >> 5, np = idx & 31;
        kpre[i] = *(const uint2*)&kbp[c * L + 2 * np];
        vpre[i] = *(const uint2*)&vbp[c * L + 2 * np];
    }
    float mpre = (t < 64) ? mp[t] : 0.f;

    __syncthreads();

    // ---- Q fragments (persistent) ----
    u32 qah[2][4], qal[2][4];
    #pragma unroll
    for (int kt = 0; kt < 2; kt++) {
        int arow = R0 + (lane & 15);
        int acol = kt * 16 + (lane >> 4) * 8;
        ldsm4(qah[kt][0], qah[kt][1], qah[kt][2], qah[kt][3], smaddr(&Qsh[arow * QP + acol]));
        ldsm4(qal[kt][0], qal[kt][1], qal[kt][2], qal[kt][3], smaddr(&Qsl[arow * QP + acol]));
    }

    float oa[4][4];
    #pragma unroll
    for (int i = 0; i < 4; i++)
        #pragma unroll
        for (int j = 0; j < 4; j++) oa[i][j] = 0.f;
    float ps0 = 0.f, ps1 = 0.f;

    for (int col0 = 0; col0 < L; col0 += 64) {
        __syncthreads();

        #pragma unroll
        for (int i = 0; i < 4; i++) {
            int idx = i * 256 + t;
            int c = idx >> 5, np = idx & 31;
            *(u32*)&Ksh[c * KP + 2 * np] = ((kpre[i].y & 0xFFFFu) << 16) | (kpre[i].x & 0xFFFFu);
            *(u32*)&Ksl[c * KP + 2 * np] = (kpre[i].y & 0xFFFF0000u) | (kpre[i].x >> 16);
            *(u32*)&Vsh[c * KP + 2 * np] = ((vpre[i].y & 0xFFFFu) << 16) | (vpre[i].x & 0xFFFFu);
            *(u32*)&Vsl[c * KP + 2 * np] = (vpre[i].y & 0xFFFF0000u) | (vpre[i].x >> 16);
        }
        if (t < 64) mk[t] = mpre;
        __syncthreads();

        int nxt = col0 + 64;
        if (nxt < L) {
            #pragma unroll
            for (int i = 0; i < 4; i++) {
                int idx = i * 256 + t;
                int c = idx >> 5, np = idx & 31;
                kpre[i] = *(const uint2*)&kbp[c * L + nxt + 2 * np];
                vpre[i] = *(const uint2*)&vbp[c * L + nxt + 2 * np];
            }
            mpre = (t < 64) ? mp[nxt + t] : 0.f;
        }

        // ---- S = Q K^T : 3-pass bf16 ----
        float sa[8][4];
        #pragma unroll
        for (int i = 0; i < 8; i++)
            #pragma unroll
            for (int j = 0; j < 4; j++) sa[i][j] = 0.f;

        #pragma unroll
        for (int kt = 0; kt < 2; kt++) {
            int brow = kt * 16 + (lane & 15);
            #pragma unroll
            for (int nb = 0; nb < 4; nb++) {
                u32 addr_off = (u32)(brow * KP + nb * 16 + (lane >> 4) * 8);
                u32 bh0, bh1, bh2, bh3, bl0, bl1, bl2, bl3;
                ldsm4t(bh0, bh1, bh2, bh3, smaddr(&Ksh[addr_off]));
                ldsm4t(bl0, bl1, bl2, bl3, smaddr(&Ksl[addr_off]));
                mma16816(sa[2 * nb + 0], qah[kt], bh0, bh1);
                mma16816(sa[2 * nb + 0], qah[kt], bl0, bl1);
                mma16816(sa[2 * nb + 0], qal[kt], bh0, bh1);
                mma16816(sa[2 * nb + 1], qah[kt], bh2, bh3);
                mma16816(sa[2 * nb + 1], qah[kt], bl2, bl3);
                mma16816(sa[2 * nb + 1], qal[kt], bh2, bh3);
            }
        }

        // ---- P = mask * exp(S); row sums; A-fragments ----
        u32 pah[4][4], pal[4][4];
        #pragma unroll
        for (int nj = 0; nj < 8; nj++) {
            float2 mm = *(const float2*)&mk[8 * nj + 2 * qid];
            float p0 = mm.x * __expf(sa[nj][0]);
            float p1 = mm.y * __expf(sa[nj][1]);
            float p2 = mm.x * __expf(sa[nj][2]);
            float p3 = mm.y * __expf(sa[nj][3]);
            ps0 += p0 + p1;
            ps1 += p2 + p3;
            u32 h01 = cvtbf2(p1, p0);
            u32 h23 = cvtbf2(p3, p2);
            float hf0 = __uint_as_float(h01 << 16);
            float hf1 = __uint_as_float(h01 & 0xFFFF0000u);
            float hf2 = __uint_as_float(h23 << 16);
            float hf3 = __uint_as_float(h23 & 0xFFFF0000u);
            u32 l01 = cvtbf2(p1 - hf1, p0 - hf0);
            u32 l23 = cvtbf2(p3 - hf3, p2 - hf2);
            int ktp = nj >> 1, od = nj & 1;
            pah[ktp][od * 2 + 0] = h01;
            pah[ktp][od * 2 + 1] = h23;
            pal[ktp][od * 2 + 0] = l01;
            pal[ktp][od * 2 + 1] = l23;
        }

        // ---- O += P V^T : 3-pass ----
        #pragma unroll
        for (int ktp = 0; ktp < 4; ktp++) {
            #pragma unroll
            for (int db = 0; db < 2; db++) {
                u32 addr_off = (u32)((db * 16 + (lane & 15)) * KP + ktp * 16 + (lane >> 4) * 8);
                u32 vh0, vh1, vh2, vh3, vl0, vl1, vl2, vl3;
                ldsm4(vh0, vh1, vh2, vh3, smaddr(&Vsh[addr_off]));
                ldsm4(vl0, vl1, vl2, vl3, smaddr(&Vsl[addr_off]));
                mma16816(oa[2 * db + 0], pah[ktp], vh0, vh2);
                mma16816(oa[2 * db + 0], pah[ktp], vl0, vl2);
                mma16816(oa[2 * db + 0], pal[ktp], vh0, vh2);
                mma16816(oa[2 * db + 1], pah[ktp], vh1, vh3);
                mma16816(oa[2 * db + 1], pah[ktp], vl1, vl3);
                mma16816(oa[2 * db + 1], pal[ktp], vh1, vh3);
            }
        }
    }

    // ---- quad-reduce row sums ----
    ps0 += __shfl_xor_sync(0xFFFFFFFFu, ps0, 1);
    ps0 += __shfl_xor_sync(0xFFFFFFFFu, ps0, 2);
    ps1 += __shfl_xor_sync(0xFFFFFFFFu, ps1, 1);
    ps1 += __shfl_xor_sync(0xFFFFFFFFu, ps1, 2);
    const float inv0 = 1.0f / (ps0 + EPSV);
    const float inv1 = 1.0f / (ps1 + EPSV);

    // ---- store packed O to g_valp[b][row][h*32 + col] ----
    const int h = bh - b * H;
    const int r = row0 + R0 + (lane >> 2);
    const int cbase = h * DK + 2 * qid;
    #pragma unroll
    for (int dj = 0; dj < 4; dj++) {
        uint2 s0, s1;
        s0.x = packsplit(oa[dj][0] * inv0);
        s0.y = packsplit(oa[dj][1] * inv0);
        s1.x = packsplit(oa[dj][2] * inv1);
        s1.y = packsplit(oa[dj][3] * inv1);
        *(uint2*)&g_valp[(size_t)(b * L + r) * D + cbase + 8 * dj] = s0;
        *(uint2*)&g_valp[(size_t)(b * L + r + 8) * D + cbase + 8 * dj] = s1;
    }
}

// ---------------------------------------------------------------------------
// Kernel 3: out = mask * (Wp @ val + bp), bf16x3 tensor-core.
// CTA 64(l) x 64(i); K=256 in 4 chunks of 64; 8 warps = 4 row-groups x 2 col-groups.
// ---------------------------------------------------------------------------
#define OP 72   // u16 pitch for out tiles

__global__ __launch_bounds__(256) void out_kernel(
    const float* __restrict__ bp, const float* __restrict__ mask,
    float* __restrict__ out)
{
    __shared__ unsigned short Ash[64 * OP];   // [l][k] hi
    __shared__ unsigned short Asl[64 * OP];   // [l][k] lo
    __shared__ unsigned short Bsh[64 * OP];   // [k][i] hi
    __shared__ unsigned short Bsl[64 * OP];   // [k][i] lo

    const int b = blockIdx.z;
    const int i0 = blockIdx.y * 64;
    const int l0 = blockIdx.x * 64;
    const int t = threadIdx.x;
    const int lane = t & 31;
    const int warp = t >> 5;
    const int R0 = (warp >> 1) * 16;     // l-rows within tile
    const int C0 = (warp & 1) * 32;      // i-cols within tile
    const int qid = lane & 3;

    const u32* __restrict__ val = g_valp + (size_t)b * L * D;

    // prefetch chunk 0
    uint2 apre[8], bpre[8];
    #pragma unroll
    for (int i = 0; i < 8; i++) {
        int idx = i * 256 + t;
        int row = idx >> 5, cp = idx & 31;
        apre[i] = *(const uint2*)&val[(l0 + row) * D + 2 * cp];
        bpre[i] = *(const uint2*)&g_wps[row * D + i0 + 2 * cp];
    }

    float oa[4][4];
    #pragma unroll
    for (int i = 0; i < 4; i++)
        #pragma unroll
        for (int j = 0; j < 4; j++) oa[i][j] = 0.f;

    for (int j0 = 0; j0 < D; j0 += 64) {
        __syncthreads();
        #pragma unroll
        for (int i = 0; i < 8; i++) {
            int idx = i * 256 + t;
            int row = idx >> 5, cp = idx & 31;
            *(u32*)&Ash[row * OP + 2 * cp] = ((apre[i].y & 0xFFFFu) << 16) | (apre[i].x & 0xFFFFu);
            *(u32*)&Asl[row * OP + 2 * cp] = (apre[i].y & 0xFFFF0000u) | (apre[i].x >> 16);
            *(u32*)&Bsh[row * OP + 2 * cp] = ((bpre[i].y & 0xFFFFu) << 16) | (bpre[i].x & 0xFFFFu);
            *(u32*)&Bsl[row * OP + 2 * cp] = (bpre[i].y & 0xFFFF0000u) | (bpre[i].x >> 16);
        }
        __syncthreads();

        int jn = j0 + 64;
        if (jn < D) {
            #pragma unroll
            for (int i = 0; i < 8; i++) {
                int idx = i * 256 + t;
                int row = idx >> 5, cp = idx & 31;
                apre[i] = *(const uint2*)&val[(l0 + row) * D + jn + 2 * cp];
                bpre[i] = *(const uint2*)&g_wps[(jn + row) * D + i0 + 2 * cp];
            }
        }

        #pragma unroll
        for (int kt = 0; kt < 4; kt++) {
            int arow = R0 + (lane & 15);
            int acol = kt * 16 + (lane >> 4) * 8;
            u32 aah[4], aal[4];
            ldsm4(aah[0], aah[1], aah[2], aah[3], smaddr(&Ash[arow * OP + acol]));
            ldsm4(aal[0], aal[1], aal[2], aal[3], smaddr(&Asl[arow * OP + acol]));

            int brow = kt * 16 + (lane & 15);
            #pragma unroll
            for (int nbp = 0; nbp < 2; nbp++) {
                u32 addr_off = (u32)(brow * OP + C0 + nbp * 16 + (lane >> 4) * 8);
                u32 bh0, bh1, bh2, bh3, bl0, bl1, bl2, bl3;
                ldsm4t(bh0, bh1, bh2, bh3, smaddr(&Bsh[addr_off]));
                ldsm4t(bl0, bl1, bl2, bl3, smaddr(&Bsl[addr_off]));
                mma16816(oa[2 * nbp + 0], aah, bh0, bh1);
                mma16816(oa[2 * nbp + 0], aah, bl0, bl1);
                mma16816(oa[2 * nbp + 0], aal, bh0, bh1);
                mma16816(oa[2 * nbp + 1], aah, bh2, bh3);
                mma16816(oa[2 * nbp + 1], aah, bl2, bl3);
                mma16816(oa[2 * nbp + 1], aal, bh2, bh3);
            }
        }
    }

    // ---- epilogue: bias + mask, fp32 stores ----
    const int r = R0 + (lane >> 2);
    const float m0 = mask[b * L + l0 + r];
    const float m1 = mask[b * L + l0 + r + 8];
    #pragma unroll
    for (int na = 0; na < 4; na++) {
        int col = i0 + C0 + na * 8 + 2 * qid;
        float2 bv = *(const float2*)&bp[col];
        *(float2*)&out[(size_t)(b * L + l0 + r) * D + col] =
            make_float2((oa[na][0] + bv.x) * m0, (oa[na][1] + bv.y) * m0);
        *(float2*)&out[(size_t)(b * L + l0 + r + 8) * D + col] =
            make_float2((oa[na][2] + bv.x) * m1, (oa[na][3] + bv.y) * m1);
    }
}

// ---------------------------------------------------------------------------
extern "C" void kernel_launch(void* const* d_in, const int* in_sizes, int n_in,
                              void* d_out, int out_size)
{
    const float* q    = (const float*)d_in[0];
    const float* k    = (const float*)d_in[1];
    const float* v    = (const float*)d_in[2];
    const float* mask = (const float*)d_in[3];
    const float* Wq   = (const float*)d_in[4];
    const float* Wk   = (const float*)d_in[5];
    const float* Wv   = (const float*)d_in[6];
    const float* Wp   = (const float*)d_in[7];
    const float* bp   = (const float*)d_in[8];
    float* out = (float*)d_out;

    cudaFuncSetAttribute(attn_kernel, cudaFuncAttributeMaxDynamicSharedMemorySize, SM_TOT);

    wsplit_kernel<<<256, 256>>>(Wp);
    proj_kernel<<<dim3(L / 512, H, BS * 3), 256>>>(q, k, v, mask, Wq, Wk, Wv);
    attn_kernel<<<dim3(L / 128, BS * H), 256, SM_TOT>>>(mask);
    out_kernel<<<dim3(L / 64, D / 64, BS), 256>>>(bp, mask, out);
}

// round 11
// speedup vs baseline: 1.3907x; 1.3907x over previous
#include <cuda_runtime.h>
#include <cuda_bf16.h>
#include <math.h>

#define BS 8
#define D 256
#define L 1024
#define H 8
#define DK 32
#define EPSV 1e-8f

typedef unsigned int u32;
typedef unsigned long long u64;

// ---- f32x2 packed-math helpers ----------------------------------------------
__device__ __forceinline__ u64 f2dup(float x) {
    u64 r; asm("mov.b64 %0, {%1, %1};" : "=l"(r) : "f"(x)); return r;
}
__device__ __forceinline__ u64 f2pack(float lo, float hi) {
    u64 r; asm("mov.b64 %0, {%1, %2};" : "=l"(r) : "f"(lo), "f"(hi)); return r;
}
__device__ __forceinline__ void fma2(u64& d, u64 a, u64 b) {
    asm("fma.rn.f32x2 %0, %1, %2, %0;" : "+l"(d) : "l"(a), "l"(b));
}
__device__ __forceinline__ float2 f2unpack(u64 v) {
    float2 f; asm("mov.b64 {%0, %1}, %2;" : "=f"(f.x), "=f"(f.y) : "l"(v)); return f;
}

// ---- tensor-core helpers ----------------------------------------------------
__device__ __forceinline__ u32 smaddr(const void* p) {
    return (u32)__cvta_generic_to_shared(p);
}
__device__ __forceinline__ void ldsm4(u32& r0, u32& r1, u32& r2, u32& r3, u32 a) {
    asm volatile("ldmatrix.sync.aligned.m8n8.x4.shared.b16 {%0,%1,%2,%3}, [%4];"
        : "=r"(r0), "=r"(r1), "=r"(r2), "=r"(r3) : "r"(a));
}
__device__ __forceinline__ void ldsm4t(u32& r0, u32& r1, u32& r2, u32& r3, u32 a) {
    asm volatile("ldmatrix.sync.aligned.m8n8.x4.trans.shared.b16 {%0,%1,%2,%3}, [%4];"
        : "=r"(r0), "=r"(r1), "=r"(r2), "=r"(r3) : "r"(a));
}
__device__ __forceinline__ void mma16816(float* c, const u32* a, u32 b0, u32 b1) {
    asm volatile("mma.sync.aligned.m16n8k16.row.col.f32.bf16.bf16.f32 "
        "{%0,%1,%2,%3}, {%4,%5,%6,%7}, {%8,%9}, {%0,%1,%2,%3};"
        : "+f"(c[0]), "+f"(c[1]), "+f"(c[2]), "+f"(c[3])
        : "r"(a[0]), "r"(a[1]), "r"(a[2]), "r"(a[3]), "r"(b0), "r"(b1));
}
__device__ __forceinline__ u32 cvtbf2(float hi, float lo) {
    u32 d; asm("cvt.rn.bf16x2.f32 %0, %1, %2;" : "=r"(d) : "f"(hi), "f"(lo)); return d;
}
// split x into (hi bf16 in low16, lo bf16 in high16)
__device__ __forceinline__ u32 packsplit(float x) {
    __nv_bfloat16 hb = __float2bfloat16(x);
    u32 hbits = (u32)__bfloat16_as_ushort(hb);
    float hf = __uint_as_float(hbits << 16);
    __nv_bfloat16 lb = __float2bfloat16(x - hf);
    return ((u32)__bfloat16_as_ushort(lb) << 16) | hbits;
}

// Scratch (device globals)
__device__ u32 g_qp[BS * D * L];    // [bh][c][l] packed (bf16 hi | lo<<16), pre-masked
__device__ u32 g_kp[BS * D * L];
__device__ u32 g_vp[BS * D * L];
__device__ float g_val[BS * L * D]; // [b][l][c]

// ---------------------------------------------------------------------------
// Kernel 1: grouped 1x1 conv projection -> packed bf16 hi/lo planes.
// ---------------------------------------------------------------------------
__global__ __launch_bounds__(256) void proj_kernel(
    const float* __restrict__ q, const float* __restrict__ k,
    const float* __restrict__ v, const float* __restrict__ mask,
    const float* __restrict__ Wq, const float* __restrict__ Wk,
    const float* __restrict__ Wv)
{
    __shared__ float wt[DK * DK];   // wt[j][i] = W[i][j]
    const int h = blockIdx.y;
    const int z = blockIdx.z;
    const int b = z / 3;
    const int which = z - b * 3;
    const int t = threadIdx.x;

    const float* __restrict__ X = (which == 0) ? q : (which == 1) ? k : v;
    const float* __restrict__ W = (which == 0) ? Wq : (which == 1) ? Wk : Wv;
    u32* __restrict__ O = (which == 0) ? g_qp : (which == 1) ? g_kp : g_vp;

    for (int idx = t; idx < DK * DK; idx += 256) {
        int j = idx >> 5, i = idx & 31;
        wt[j * DK + i] = W[h * DK * DK + i * DK + j];
    }
    __syncthreads();

    const int l0 = blockIdx.x * 512 + t * 2;
    const float mv0 = mask[b * L + l0];
    const float mv1 = mask[b * L + l0 + 1];
    const int xbase = (b * D + h * DK) * L + l0;
    const int obase = (b * H + h) * DK * L + l0;

    u64 acc[2][16];
    #pragma unroll
    for (int p = 0; p < 2; p++)
        #pragma unroll
        for (int i = 0; i < 16; i++) acc[p][i] = 0ull;

    #pragma unroll
    for (int j = 0; j < DK; j++) {
        float2 xv = *(const float2*)&X[xbase + j * L];
        u64 x0 = f2dup(xv.x);
        u64 x1 = f2dup(xv.y);
        #pragma unroll
        for (int q4 = 0; q4 < 8; q4++) {
            float4 w4 = *(const float4*)&wt[j * DK + q4 * 4];
            u64 wp0 = f2pack(w4.x, w4.y);
            u64 wp1 = f2pack(w4.z, w4.w);
            fma2(acc[0][q4 * 2 + 0], x0, wp0);
            fma2(acc[0][q4 * 2 + 1], x0, wp1);
            fma2(acc[1][q4 * 2 + 0], x1, wp0);
            fma2(acc[1][q4 * 2 + 1], x1, wp1);
        }
    }

    #pragma unroll
    for (int ip = 0; ip < 16; ip++) {
        float2 r0 = f2unpack(acc[0][ip]);
        float2 r1 = f2unpack(acc[1][ip]);
        uint2 s0, s1;
        s0.x = packsplit(r0.x * mv0); s0.y = packsplit(r1.x * mv1);
        s1.x = packsplit(r0.y * mv0); s1.y = packsplit(r1.y * mv1);
        *(uint2*)&O[obase + (2 * ip + 0) * L] = s0;
        *(uint2*)&O[obase + (2 * ip + 1) * L] = s1;
    }
}

// ---------------------------------------------------------------------------
// Kernel 2: fused attention, bf16x3 tensor-core. Restructured per-16-col
// chunks (QK -> softmax -> PV immediately) so live registers stay ~100,
// enabling 2 CTAs/SM for latency hiding. Same math as R9.
// ---------------------------------------------------------------------------
#define QP 48
#define KP 72
#define SM_QSH 0
#define SM_QSL 12288
#define SM_KSH 24576
#define SM_KSL 29184
#define SM_VSH 33792
#define SM_VSL 38400
#define SM_MK  43008
#define SM_TOT 43264

__global__ __launch_bounds__(256, 2) void attn_kernel(const float* __restrict__ mask)
{
    extern __shared__ char smb[];
    unsigned short* Qsh = (unsigned short*)(smb + SM_QSH);  // [m][c]
    unsigned short* Qsl = (unsigned short*)(smb + SM_QSL);
    unsigned short* Ksh = (unsigned short*)(smb + SM_KSH);  // [c][n]
    unsigned short* Ksl = (unsigned short*)(smb + SM_KSL);
    unsigned short* Vsh = (unsigned short*)(smb + SM_VSH);  // [d][n]
    unsigned short* Vsl = (unsigned short*)(smb + SM_VSL);
    float* mk = (float*)(smb + SM_MK);

    const int bh = blockIdx.y;
    const int b = bh / H;
    const int row0 = blockIdx.x * 128;

    const u32* __restrict__ qb = g_qp + bh * DK * L;
    const u32* __restrict__ kbp = g_kp + bh * DK * L;
    const u32* __restrict__ vbp = g_vp + bh * DK * L;
    const float* __restrict__ mp = mask + b * L;

    const int t = threadIdx.x;
    const int lane = t & 31;
    const int warp = t >> 5;
    const int R0 = warp * 16;
    const int qid = lane & 3;

    // ---- Q fill: [m][c] hi/lo planes ----
    #pragma unroll
    for (int i = 0; i < 8; i++) {
        int idx = i * 256 + t;
        int m = idx >> 4, cp = idx & 15;
        u32 q0 = qb[(2 * cp + 0) * L + row0 + m];
        u32 q1 = qb[(2 * cp + 1) * L + row0 + m];
        *(u32*)&Qsh[m * QP + 2 * cp] = ((q1 & 0xFFFFu) << 16) | (q0 & 0xFFFFu);
        *(u32*)&Qsl[m * QP + 2 * cp] = (q1 & 0xFFFF0000u) | (q0 >> 16);
    }

    // ---- prefetch K/V tile 0 ----
    uint2 kpre[4], vpre[4];
    #pragma unroll
    for (int i = 0; i < 4; i++) {
        int idx = i * 256 + t;
        int c = idx >> 5, np = idx & 31;
        kpre[i] = *(const uint2*)&kbp[c * L + 2 * np];
        vpre[i] = *(const uint2*)&vbp[c * L + 2 * np];
    }
    float mpre = (t < 64) ? mp[t] : 0.f;

    __syncthreads();

    // ---- Q fragments (persistent) ----
    u32 qah[2][4], qal[2][4];
    #pragma unroll
    for (int kt = 0; kt < 2; kt++) {
        int arow = R0 + (lane & 15);
        int acol = kt * 16 + (lane >> 4) * 8;
        ldsm4(qah[kt][0], qah[kt][1], qah[kt][2], qah[kt][3], smaddr(&Qsh[arow * QP + acol]));
        ldsm4(qal[kt][0], qal[kt][1], qal[kt][2], qal[kt][3], smaddr(&Qsl[arow * QP + acol]));
    }

    float oa[4][4];
    #pragma unroll
    for (int i = 0; i < 4; i++)
        #pragma unroll
        for (int j = 0; j < 4; j++) oa[i][j] = 0.f;
    float ps0 = 0.f, ps1 = 0.f;

    for (int col0 = 0; col0 < L; col0 += 64) {
        __syncthreads();

        #pragma unroll
        for (int i = 0; i < 4; i++) {
            int idx = i * 256 + t;
            int c = idx >> 5, np = idx & 31;
            *(u32*)&Ksh[c * KP + 2 * np] = ((kpre[i].y & 0xFFFFu) << 16) | (kpre[i].x & 0xFFFFu);
            *(u32*)&Ksl[c * KP + 2 * np] = (kpre[i].y & 0xFFFF0000u) | (kpre[i].x >> 16);
            *(u32*)&Vsh[c * KP + 2 * np] = ((vpre[i].y & 0xFFFFu) << 16) | (vpre[i].x & 0xFFFFu);
            *(u32*)&Vsl[c * KP + 2 * np] = (vpre[i].y & 0xFFFF0000u) | (vpre[i].x >> 16);
        }
        if (t < 64) mk[t] = mpre;
        __syncthreads();

        int nxt = col0 + 64;
        if (nxt < L) {
            #pragma unroll
            for (int i = 0; i < 4; i++) {
                int idx = i * 256 + t;
                int c = idx >> 5, np = idx & 31;
                kpre[i] = *(const uint2*)&kbp[c * L + nxt + 2 * np];
                vpre[i] = *(const uint2*)&vbp[c * L + nxt + 2 * np];
            }
            mpre = (t < 64) ? mp[nxt + t] : 0.f;
        }

        // ---- per-16-col chunk: QK -> softmax -> PV (low register footprint) ----
        #pragma unroll
        for (int ktp = 0; ktp < 4; ktp++) {
            // S for this chunk: 2 n8-atoms
            float sa[2][4];
            #pragma unroll
            for (int i = 0; i < 2; i++)
                #pragma unroll
                for (int j = 0; j < 4; j++) sa[i][j] = 0.f;

            #pragma unroll
            for (int kt = 0; kt < 2; kt++) {
                u32 addr_off = (u32)((kt * 16 + (lane & 15)) * KP + ktp * 16 + (lane >> 4) * 8);
                u32 bh0, bh1, bh2, bh3, bl0, bl1, bl2, bl3;
                ldsm4t(bh0, bh1, bh2, bh3, smaddr(&Ksh[addr_off]));
                ldsm4t(bl0, bl1, bl2, bl3, smaddr(&Ksl[addr_off]));
                mma16816(sa[0], qah[kt], bh0, bh1);
                mma16816(sa[0], qah[kt], bl0, bl1);
                mma16816(sa[0], qal[kt], bh0, bh1);
                mma16816(sa[1], qah[kt], bh2, bh3);
                mma16816(sa[1], qah[kt], bl2, bl3);
                mma16816(sa[1], qal[kt], bh2, bh3);
            }

            // P fragment for this chunk (A of k16)
            u32 pah[4], pal[4];
            #pragma unroll
            for (int od = 0; od < 2; od++) {
                int nj = 2 * ktp + od;
                float2 mm = *(const float2*)&mk[8 * nj + 2 * qid];
                float p0 = mm.x * __expf(sa[od][0]);
                float p1 = mm.y * __expf(sa[od][1]);
                float p2 = mm.x * __expf(sa[od][2]);
                float p3 = mm.y * __expf(sa[od][3]);
                ps0 += p0 + p1;
                ps1 += p2 + p3;
                u32 h01 = cvtbf2(p1, p0);
                u32 h23 = cvtbf2(p3, p2);
                float hf0 = __uint_as_float(h01 << 16);
                float hf1 = __uint_as_float(h01 & 0xFFFF0000u);
                float hf2 = __uint_as_float(h23 << 16);
                float hf3 = __uint_as_float(h23 & 0xFFFF0000u);
                pah[od * 2 + 0] = h01;
                pah[od * 2 + 1] = h23;
                pal[od * 2 + 0] = cvtbf2(p1 - hf1, p0 - hf0);
                pal[od * 2 + 1] = cvtbf2(p3 - hf3, p2 - hf2);
            }

            // PV for this chunk: k16 = these 16 n-cols
            #pragma unroll
            for (int db = 0; db < 2; db++) {
                u32 addr_off = (u32)((db * 16 + (lane & 15)) * KP + ktp * 16 + (lane >> 4) * 8);
                u32 vh0, vh1, vh2, vh3, vl0, vl1, vl2, vl3;
                ldsm4(vh0, vh1, vh2, vh3, smaddr(&Vsh[addr_off]));
                ldsm4(vl0, vl1, vl2, vl3, smaddr(&Vsl[addr_off]));
                mma16816(oa[2 * db + 0], pah, vh0, vh2);
                mma16816(oa[2 * db + 0], pah, vl0, vl2);
                mma16816(oa[2 * db + 0], pal, vh0, vh2);
                mma16816(oa[2 * db + 1], pah, vh1, vh3);
                mma16816(oa[2 * db + 1], pah, vl1, vl3);
                mma16816(oa[2 * db + 1], pal, vh1, vh3);
            }
        }
    }

    // ---- quad-reduce row sums ----
    ps0 += __shfl_xor_sync(0xFFFFFFFFu, ps0, 1);
    ps0 += __shfl_xor_sync(0xFFFFFFFFu, ps0, 2);
    ps1 += __shfl_xor_sync(0xFFFFFFFFu, ps1, 1);
    ps1 += __shfl_xor_sync(0xFFFFFFFFu, ps1, 2);
    const float inv0 = 1.0f / (ps0 + EPSV);
    const float inv1 = 1.0f / (ps1 + EPSV);

    // ---- store O to g_val[b][row][h*32 + col] (fp32, as in R9) ----
    const int h = bh - b * H;
    const int r = row0 + R0 + (lane >> 2);
    const int cbase = h * DK + 2 * qid;
    #pragma unroll
    for (int dj = 0; dj < 4; dj++) {
        *(float2*)&g_val[(size_t)(b * L + r) * D + cbase + 8 * dj] =
            make_float2(oa[dj][0] * inv0, oa[dj][1] * inv0);
        *(float2*)&g_val[(size_t)(b * L + r + 8) * D + cbase + 8 * dj] =
            make_float2(oa[dj][2] * inv1, oa[dj][3] * inv1);
    }
}

// ---------------------------------------------------------------------------
// Kernel 3: out = mask * (Wp @ val + bp)  (R9 fp32 FFMA2 version)
// ---------------------------------------------------------------------------
#define OK_LD 68

__global__ __launch_bounds__(256) void out_kernel(
    const float* __restrict__ Wp, const float* __restrict__ bp,
    const float* __restrict__ mask, float* __restrict__ out)
{
    __shared__ __align__(16) float As[32 * OK_LD];   // [j][l]
    __shared__ __align__(16) float Bsm[32 * OK_LD];  // [j][i]

    const int b = blockIdx.z;
    const int i0 = blockIdx.y * 64;
    const int l0 = blockIdx.x * 64;
    const int t = threadIdx.x;
    const int rg = t >> 4, cg = t & 15;
    const int lr = rg * 4, ic = cg * 4;

    const float* __restrict__ val = g_val + b * L * D;

    int fl[8], fj[8];
    #pragma unroll
    for (int i = 0; i < 8; i++) {
        int idx = i * 256 + t;
        fl[i] = idx >> 5;
        fj[i] = idx & 31;
    }

    float ab[8], bb[8];
    #pragma unroll
    for (int i = 0; i < 8; i++) {
        ab[i] = val[(l0 + fl[i]) * D + fj[i]];
        bb[i] = Wp[(i0 + fl[i]) * D + fj[i]];
    }

    u64 acc2[2][4];
    #pragma unroll
    for (int p = 0; p < 2; p++)
        #pragma unroll
        for (int i = 0; i < 4; i++) acc2[p][i] = 0ull;

    for (int j0 = 0; j0 < D; j0 += 32) {
        __syncthreads();
        #pragma unroll
        for (int i = 0; i < 8; i++) {
            As[fj[i] * OK_LD + fl[i]] = ab[i];
            Bsm[fj[i] * OK_LD + fl[i]] = bb[i];
        }
        __syncthreads();

        int jn = j0 + 32;
        if (jn < D) {
            #pragma unroll
            for (int i = 0; i < 8; i++) {
                ab[i] = val[(l0 + fl[i]) * D + jn + fj[i]];
                bb[i] = Wp[(i0 + fl[i]) * D + jn + fj[i]];
            }
        }

        #pragma unroll
        for (int kk = 0; kk < 32; kk++) {
            float4 av = *(const float4*)&As[kk * OK_LD + lr];
            float4 bv = *(const float4*)&Bsm[kk * OK_LD + ic];
            u64 a01 = f2pack(av.x, av.y);
            u64 a23 = f2pack(av.z, av.w);
            u64 b0 = f2dup(bv.x), b1 = f2dup(bv.y), b2 = f2dup(bv.z), b3 = f2dup(bv.w);
            fma2(acc2[0][0], a01, b0); fma2(acc2[1][0], a23, b0);
            fma2(acc2[0][1], a01, b1); fma2(acc2[1][1], a23, b1);
            fma2(acc2[0][2], a01, b2); fma2(acc2[1][2], a23, b2);
            fma2(acc2[0][3], a01, b3); fma2(acc2[1][3], a23, b3);
        }
    }

    const float bv0 = bp[i0 + ic + 0];
    const float bv1 = bp[i0 + ic + 1];
    const float bv2 = bp[i0 + ic + 2];
    const float bv3 = bp[i0 + ic + 3];

    float2 c0r = f2unpack(acc2[0][0]), c1r = f2unpack(acc2[0][1]);
    float2 c2r = f2unpack(acc2[0][2]), c3r = f2unpack(acc2[0][3]);
    float2 d0r = f2unpack(acc2[1][0]), d1r = f2unpack(acc2[1][1]);
    float2 d2r = f2unpack(acc2[1][2]), d3r = f2unpack(acc2[1][3]);

    float rows[4][4] = {
        {c0r.x, c1r.x, c2r.x, c3r.x},
        {c0r.y, c1r.y, c2r.y, c3r.y},
        {d0r.x, d1r.x, d2r.x, d3r.x},
        {d0r.y, d1r.y, d2r.y, d3r.y},
    };

    #pragma unroll
    for (int p = 0; p < 4; p++) {
        float mv = mask[b * L + l0 + lr + p];
        float4 r;
        r.x = (rows[p][0] + bv0) * mv;
        r.y = (rows[p][1] + bv1) * mv;
        r.z = (rows[p][2] + bv2) * mv;
        r.w = (rows[p][3] + bv3) * mv;
        *(float4*)&out[((size_t)(b * L + l0 + lr + p)) * D + i0 + ic] = r;
    }
}

// ---------------------------------------------------------------------------
extern "C" void kernel_launch(void* const* d_in, const int* in_sizes, int n_in,
                              void* d_out, int out_size)
{
    const float* q    = (const float*)d_in[0];
    const float* k    = (const float*)d_in[1];
    const float* v    = (const float*)d_in[2];
    const float* mask = (const float*)d_in[3];
    const float* Wq   = (const float*)d_in[4];
    const float* Wk   = (const float*)d_in[5];
    const float* Wv   = (const float*)d_in[6];
    const float* Wp   = (const float*)d_in[7];
    const float* bp   = (const float*)d_in[8];
    float* out = (float*)d_out;

    cudaFuncSetAttribute(attn_kernel, cudaFuncAttributeMaxDynamicSharedMemorySize, SM_TOT);

    proj_kernel<<<dim3(L / 512, H, BS * 3), 256>>>(q, k, v, mask, Wq, Wk, Wv);
    attn_kernel<<<dim3(L / 128, BS * H), 256, SM_TOT>>>(mask);
    out_kernel<<<dim3(L / 64, D / 64, BS), 256>>>(Wp, bp, mask, out);
}